// round 16
// baseline (speedup 1.0000x reference)
#include <cuda_runtime.h>
#include <cuda_bf16.h>
#include <cstdint>

// Problem constants
#define BB 4
#define NN 4096
#define CC 64
#define BN (BB * NN)
#define CHUNK 512
#define NCH (NN / CHUNK)          // 8 chunks per batch
#define NB 256                    // grid size (fixed, all blocks co-resident)
#define BMW 128                   // bitmap words per (batch,class): 4096 bits

#define TARGETF 560.0f
#define MIN_BOXF 5.0f
#define IOU_THRF 0.2f
#define CONF_THRF 0.001f
#define BOX_CONF_THRF 0.01f
#define MAX_WHF 4096.0f

#define CAP 256                    // per-class member cap for fast path
#define WSTRIDE 8                  // mask words per row (CAP/32)

// ------------------------- scratch (static device memory) -------------------
__device__ float4 g_cbox[BN];                      // clipped boxes, orig order
__device__ float  g_key[BN];                       // valid ? conf : -1
__device__ __align__(128) unsigned char g_tag[BN]; // valid ? cls : 255
__device__ unsigned long long g_ck[BN];            // sorted key chunks
__device__ float4 g_sbox[BN];                      // boxes in sorted order
__device__ float  g_sconf[BN];                     // conf in sorted order
__device__ unsigned int g_bm[BB * CC * BMW];       // per-(b,c) rank bitmaps

// grid barrier state (self-resetting each launch; zero-initialized)
__device__ int g_cnt[4];
__device__ int g_done[4];

// ------------------------- grid-wide barrier --------------------------------
__device__ __forceinline__ void gbar(int i) {
    __syncthreads();
    if (threadIdx.x == 0) {
        __threadfence();
        atomicAdd(&g_cnt[i], 1);
        while (*(volatile int*)&g_cnt[i] < NB) __nanosleep(64);
        __threadfence();
        int d = atomicAdd(&g_done[i], 1);
        if (d == NB - 1) {
            *(volatile int*)&g_cnt[i]  = 0;
            *(volatile int*)&g_done[i] = 0;
            __threadfence();
        }
    }
    __syncthreads();
}

// ------------------------- register bitonic helpers -------------------------
__device__ __forceinline__ unsigned long long kmin(unsigned long long a,
                                                   unsigned long long b) {
    return a < b ? a : b;
}
__device__ __forceinline__ unsigned long long kmax(unsigned long long a,
                                                   unsigned long long b) {
    return a > b ? a : b;
}
__device__ __forceinline__ void stage_j(unsigned long long v[4], int i0,
                                        int lane, int k, int j) {
    if (j >= 4) {
        int m = j >> 2;
        #pragma unroll
        for (int r = 0; r < 4; r++) {
            unsigned long long other = __shfl_xor_sync(0xffffffffu, v[r], m);
            bool up = (((i0 + r) & k) == 0);
            bool keepmin = (((lane & m) == 0) == up);
            v[r] = keepmin ? kmin(v[r], other) : kmax(v[r], other);
        }
    } else if (j == 2) {
        #pragma unroll
        for (int r = 0; r < 2; r++) {
            bool up = (((i0 + r) & k) == 0);
            unsigned long long a = v[r], c = v[r + 2];
            if ((a > c) == up) { v[r] = c; v[r + 2] = a; }
        }
    } else {
        #pragma unroll
        for (int r = 0; r < 4; r += 2) {
            bool up = (((i0 + r) & k) == 0);
            unsigned long long a = v[r], c = v[r + 1];
            if ((a > c) == up) { v[r] = c; v[r + 1] = a; }
        }
    }
}

// ------------------------- fused kernel -------------------------------------
__global__ void __launch_bounds__(256) fused_all(const float* __restrict__ boxes,
                                                 const float* __restrict__ scores,
                                                 const float* __restrict__ preds,
                                                 float* __restrict__ out) {
    int blk  = blockIdx.x;
    int t    = threadIdx.x;
    int lane = t & 31;
    int wid  = t >> 5;

    __shared__ union {
        unsigned long long sortbuf[CHUNK];     // P2: 4KB
        unsigned long long mergebuf[NN];       // P3: 32KB
        struct {
            float sx1[CAP], sy1[CAP], sx2[CAP], sy2[CAP];
            float sar[CAP], scf[CAP];
            int   spos[CAP];
            unsigned int smask[CAP * WSTRIDE];
            unsigned int mbw[BMW];
            unsigned int supw[BMW];
        } nms;                                  // ~16KB
    } sm;
    __shared__ int warp_tot[8];
    __shared__ unsigned int keepw[WSTRIDE];

    // ================= Phase 1: conf/argmax/clip/valid + bitmap zero ========
    {
        int zi = blk * 256 + t;
        if (zi < BB * CC * BMW) g_bm[zi] = 0;

        int half = lane >> 4;
        int hl   = lane & 15;
        #pragma unroll
        for (int pass = 0; pass < 4; pass++) {
            int box = blk * 64 + pass * 16 + wid * 2 + half;
            float s = scores[box];
            const float4* p4 =
                reinterpret_cast<const float4*>(preds + (size_t)box * CC);
            float4 pv = p4[hl];
            float bv; int bi;
            {
                float v0 = __fmul_rn(pv.x, s);
                float v1 = __fmul_rn(pv.y, s);
                float v2 = __fmul_rn(pv.z, s);
                float v3 = __fmul_rn(pv.w, s);
                bv = v0; bi = hl * 4;
                if (v1 > bv) { bv = v1; bi = hl * 4 + 1; }
                if (v2 > bv) { bv = v2; bi = hl * 4 + 2; }
                if (v3 > bv) { bv = v3; bi = hl * 4 + 3; }
            }
            #pragma unroll
            for (int o = 8; o > 0; o >>= 1) {
                float ov = __shfl_xor_sync(0xffffffffu, bv, o);
                int   oi = __shfl_xor_sync(0xffffffffu, bi, o);
                if (ov > bv || (ov == bv && oi < bi)) { bv = ov; bi = oi; }
            }
            if (hl == 0) {
                float4 bx = reinterpret_cast<const float4*>(boxes)[box];
                float x1 = fminf(fmaxf(bx.x, 0.0f), TARGETF);
                float y1 = fminf(fmaxf(bx.y, 0.0f), TARGETF);
                float x2 = fminf(fmaxf(bx.z, 0.0f), TARGETF);
                float y2 = fminf(fmaxf(bx.w, 0.0f), TARGETF);
                float w = __fsub_rn(x2, x1);
                float h = __fsub_rn(y2, y1);
                int valid = (s > BOX_CONF_THRF) && (w > MIN_BOXF)
                            && (h > MIN_BOXF) && (bv > CONF_THRF);
                g_cbox[box] = make_float4(x1, y1, x2, y2);
                g_key[box]  = valid ? bv : -1.0f;
                g_tag[box]  = valid ? (unsigned char)bi : (unsigned char)255;
            }
        }
    }
    gbar(0);

    // ================= Phase 2: chunk sort (blocks 0..31) ===================
    if (blk < 32) {
        int b  = blk >> 3;
        int ch = blk & 7;
        unsigned long long* sk = sm.sortbuf;

        #pragma unroll
        for (int u = 0; u < 2; u++) {
            int i   = t + u * 256;
            int idx = ch * CHUNK + i;
            unsigned int x = __float_as_uint(g_key[b * NN + idx]);
            x = (x & 0x80000000u) ? ~x : (x | 0x80000000u);
            sk[i] = ((unsigned long long)(~x) << 32) | (unsigned int)idx;
        }
        __syncthreads();

        int i0 = ((t >> 5) << 7) + (lane << 2);   // valid for t<128
        if (t < 128) {
            unsigned long long v[4];
            #pragma unroll
            for (int r = 0; r < 4; r++) v[r] = sk[i0 + r];
            #pragma unroll
            for (int k = 2; k <= 128; k <<= 1)
                for (int j = k >> 1; j >= 1; j >>= 1)
                    stage_j(v, i0, lane, k, j);
            #pragma unroll
            for (int r = 0; r < 4; r++) sk[i0 + r] = v[r];
        }
        __syncthreads();

        #pragma unroll
        for (int k = 256; k <= CHUNK; k <<= 1) {
            for (int j = k >> 1; j >= 128; j >>= 1) {
                int p   = t;                         // exactly 256 pairs
                int i   = ((p & ~(j - 1)) << 1) | (p & (j - 1));
                int ixj = i | j;
                bool up = ((i & k) == 0);
                unsigned long long a = sk[i], c = sk[ixj];
                if ((a > c) == up) { sk[i] = c; sk[ixj] = a; }
                __syncthreads();
            }
            if (t < 128) {
                unsigned long long v[4];
                #pragma unroll
                for (int r = 0; r < 4; r++) v[r] = sk[i0 + r];
                #pragma unroll
                for (int j = 64; j >= 1; j >>= 1)
                    stage_j(v, i0, lane, k, j);
                #pragma unroll
                for (int r = 0; r < 4; r++) sk[i0 + r] = v[r];
            }
            __syncthreads();
        }

        #pragma unroll
        for (int u = 0; u < 2; u++) {
            int i = t + u * 256;
            g_ck[b * NN + ch * CHUNK + i] = sk[i];
        }
    }
    gbar(1);

    // ========== Phase 3: rank-merge + scatter + zero + bitmap (blocks 0..63)
    if (blk < 64) {
        int b   = blk >> 4;
        int sub = blk & 15;
        unsigned long long* sck = sm.mergebuf;
        const unsigned long long* ck = g_ck + b * NN;
        #pragma unroll
        for (int u = 0; u < 16; u++) sck[t + u * 256] = ck[t + u * 256];
        __syncthreads();

        int e   = sub * 256 + t;
        int ch2 = e >> 9;
        int pos = e & (CHUNK - 1);
        unsigned long long K = sck[e];
        int rank = pos;

        int lo[NCH], hi[NCH];
        #pragma unroll
        for (int c2 = 0; c2 < NCH; c2++) { lo[c2] = 0; hi[c2] = (c2 == ch2) ? 0 : CHUNK; }
        #pragma unroll
        for (int it = 0; it < 10; it++) {
            #pragma unroll
            for (int c2 = 0; c2 < NCH; c2++) {
                if (lo[c2] < hi[c2]) {
                    int mid = (lo[c2] + hi[c2]) >> 1;
                    unsigned long long v = sck[c2 * CHUNK + mid];
                    if (v < K) lo[c2] = mid + 1; else hi[c2] = mid;
                }
            }
        }
        #pragma unroll
        for (int c2 = 0; c2 < NCH; c2++) rank += lo[c2];

        int idx = (int)(K & 0xffffffffull);
        int d = b * NN + rank;
        int s = b * NN + idx;

        float* o = out + (size_t)d * 6;
        o[0] = 0.0f; o[1] = 0.0f; o[2] = 0.0f;
        o[3] = 0.0f; o[4] = 0.0f; o[5] = 0.0f;

        g_sbox[d] = g_cbox[s];
        unsigned char tg = g_tag[s];
        if (tg != 255)
            atomicOr(&g_bm[((b * CC + (int)tg) * BMW) + (rank >> 5)],
                     1u << (rank & 31));
        unsigned int up = ~(unsigned int)(K >> 32);
        unsigned int uu = (up & 0x80000000u) ? (up & 0x7fffffffu) : ~up;
        g_sconf[d] = __uint_as_float(uu);
    }
    gbar(2);

    // ================= Phase 4: per-(batch,class) NMS via bitmap ============
    {
        int b = blk >> 6;
        int c = blk & 63;

        unsigned int mw = 0;
        if (t < BMW) mw = g_bm[(b * CC + c) * BMW + t];
        if (t < BMW) sm.nms.mbw[t] = mw;
        int cnt = __popc(mw);

        int inc = cnt;
        #pragma unroll
        for (int o = 1; o < 32; o <<= 1) {
            int tmp = __shfl_up_sync(0xffffffffu, inc, o);
            if (lane >= o) inc += tmp;
        }
        if (lane == 31) warp_tot[wid] = inc;
        __syncthreads();

        int M = 0, pre = 0;
        #pragma unroll
        for (int w = 0; w < 8; w++) {
            int v = warp_tot[w];
            if (w < wid) pre += v;
            M += v;
        }
        if (M == 0) return;

        float offc = (float)c * MAX_WHF;   // exact in fp32
        int off = pre + (inc - cnt);
        int base = t * 32;

        if (M <= CAP) {
            // ---- gather members into compacted slots (bitmap-driven) ----
            unsigned int r = mw;
            while (r) {
                int q = __ffs(r) - 1;
                int pos = base + q;
                int slot = off++;
                sm.nms.spos[slot] = pos;
                sm.nms.scf[slot]  = g_sconf[b * NN + pos];
                float4 bx = g_sbox[b * NN + pos];
                sm.nms.sx1[slot] = bx.x; sm.nms.sy1[slot] = bx.y;
                sm.nms.sx2[slot] = bx.z; sm.nms.sy2[slot] = bx.w;
                float ox1 = __fadd_rn(bx.x, offc), oy1 = __fadd_rn(bx.y, offc);
                float ox2 = __fadd_rn(bx.z, offc), oy2 = __fadd_rn(bx.w, offc);
                sm.nms.sar[slot] = __fmul_rn(__fsub_rn(ox2, ox1),
                                             __fsub_rn(oy2, oy1));
                r &= r - 1;
            }
            __syncthreads();

            // ---- pairwise IoU>thr bit-matrix (upper-triangle words) ----
            int W = (M + 31) >> 5;
            for (int i = wid; i < M; i += 8) {
                float ix1 = __fadd_rn(sm.nms.sx1[i], offc);
                float iy1 = __fadd_rn(sm.nms.sy1[i], offc);
                float ix2 = __fadd_rn(sm.nms.sx2[i], offc);
                float iy2 = __fadd_rn(sm.nms.sy2[i], offc);
                float ai  = sm.nms.sar[i];
                for (int cw = (i >> 5); cw < W; cw++) {
                    int j = cw * 32 + lane;
                    bool s = false;
                    if (j < M && j > i) {
                        float jx1 = __fadd_rn(sm.nms.sx1[j], offc);
                        float jy1 = __fadd_rn(sm.nms.sy1[j], offc);
                        float jx2 = __fadd_rn(sm.nms.sx2[j], offc);
                        float jy2 = __fadd_rn(sm.nms.sy2[j], offc);
                        float aj  = sm.nms.sar[j];
                        float ltx = fmaxf(ix1, jx1), lty = fmaxf(iy1, jy1);
                        float rbx = fminf(ix2, jx2), rby = fminf(iy2, jy2);
                        float w = fmaxf(__fsub_rn(rbx, ltx), 0.0f);
                        float h = fmaxf(__fsub_rn(rby, lty), 0.0f);
                        float inter = __fmul_rn(w, h);
                        float denom = __fadd_rn(__fsub_rn(__fadd_rn(ai, aj),
                                                          inter), 1e-9f);
                        s = __fdiv_rn(inter, denom) > IOU_THRF;
                    }
                    unsigned int bal = __ballot_sync(0xffffffffu, s);
                    if (lane == 0) sm.nms.smask[i * WSTRIDE + cw] = bal;
                }
            }
            __syncthreads();

            // ---- warp-cooperative ffs greedy (warp 0) ----
            if (wid == 0) {
                int W2 = (M + 31) >> 5;
                unsigned int rem = 0;
                if (lane < W2) {
                    int rb = M - lane * 32;
                    rem = (rb >= 32) ? 0xffffffffu : ((1u << rb) - 1u);
                }
                unsigned int keep = 0;
                for (;;) {
                    unsigned int bal = __ballot_sync(0xffffffffu, rem != 0);
                    if (!bal) break;
                    int src = __ffs(bal) - 1;
                    unsigned int word = __shfl_sync(0xffffffffu, rem, src);
                    int i = (src << 5) + __ffs(word) - 1;
                    if (lane == src) {
                        keep |= 1u << (i & 31);
                        rem  &= ~(1u << (i & 31));
                    }
                    unsigned int supr = (lane < W2 && lane >= (i >> 5))
                                      ? sm.nms.smask[i * WSTRIDE + lane] : 0u;
                    rem &= ~supr;
                }
                if (lane < WSTRIDE) keepw[lane] = (lane < W2) ? keep : 0u;
            }
            __syncthreads();

            // ---- write kept rows DIRECTLY to output ----
            for (int m = t; m < M; m += 256) {
                if ((keepw[m >> 5] >> (m & 31)) & 1u) {
                    float* o = out + ((size_t)b * NN + sm.nms.spos[m]) * 6;
                    o[0] = sm.nms.sx1[m]; o[1] = sm.nms.sy1[m];
                    o[2] = sm.nms.sx2[m]; o[3] = sm.nms.sy2[m];
                    o[4] = sm.nms.scf[m]; o[5] = (float)c;
                }
            }
            return;
        }

        // ---- Fallback (M > CAP): bitmap greedy in rank order (never hit) ---
        if (t < BMW) sm.nms.supw[t] = 0;
        __syncthreads();
        for (int w = 0; w < BMW; w++) {
            unsigned int avail = sm.nms.mbw[w] & ~sm.nms.supw[w];
            while (avail) {
                int bit = __ffs(avail) - 1;
                int pos = w * 32 + bit;
                float4 bi = g_sbox[b * NN + pos];
                float ix1 = __fadd_rn(bi.x, offc), iy1 = __fadd_rn(bi.y, offc);
                float ix2 = __fadd_rn(bi.z, offc), iy2 = __fadd_rn(bi.w, offc);
                float ai  = __fmul_rn(__fsub_rn(ix2, ix1), __fsub_rn(iy2, iy1));
                if (t == 0) {
                    float* o = out + ((size_t)b * NN + pos) * 6;
                    o[0] = bi.x; o[1] = bi.y; o[2] = bi.z; o[3] = bi.w;
                    o[4] = g_sconf[b * NN + pos];
                    o[5] = (float)c;
                }
                if (t < BMW) {
                    unsigned int mymb = sm.nms.mbw[t], mysup = sm.nms.supw[t];
                    unsigned int work = mymb & ~mysup;
                    while (work) {
                        int q = __ffs(work) - 1;
                        work &= work - 1;
                        int j = t * 32 + q;
                        if (j <= pos) continue;
                        float4 bj = g_sbox[b * NN + j];
                        float jx1 = __fadd_rn(bj.x, offc), jy1 = __fadd_rn(bj.y, offc);
                        float jx2 = __fadd_rn(bj.z, offc), jy2 = __fadd_rn(bj.w, offc);
                        float aj  = __fmul_rn(__fsub_rn(jx2, jx1),
                                              __fsub_rn(jy2, jy1));
                        float ltx = fmaxf(ix1, jx1), lty = fmaxf(iy1, jy1);
                        float rbx = fminf(ix2, jx2), rby = fminf(iy2, jy2);
                        float wq = fmaxf(__fsub_rn(rbx, ltx), 0.0f);
                        float hq = fmaxf(__fsub_rn(rby, lty), 0.0f);
                        float inter = __fmul_rn(wq, hq);
                        float denom = __fadd_rn(__fsub_rn(__fadd_rn(ai, aj),
                                                          inter), 1e-9f);
                        if (__fdiv_rn(inter, denom) > IOU_THRF)
                            mysup |= 1u << q;
                    }
                    sm.nms.supw[t] = mysup;
                }
                __syncthreads();
                avail = sm.nms.mbw[w] & ~sm.nms.supw[w];
                avail &= ~((bit == 31) ? 0xffffffffu : ((1u << (bit + 1)) - 1u));
            }
            __syncthreads();
        }
    }
}

// ------------------------- launch -------------------------------------------
extern "C" void kernel_launch(void* const* d_in, const int* in_sizes, int n_in,
                              void* d_out, int out_size) {
    const float *boxes = nullptr, *scores = nullptr, *preds = nullptr;
    for (int i = 0; i < n_in; i++) {
        if (in_sizes[i] == BN * 4)       boxes  = (const float*)d_in[i];
        else if (in_sizes[i] == BN)      scores = (const float*)d_in[i];
        else if (in_sizes[i] == BN * CC) preds  = (const float*)d_in[i];
    }
    float* out = (float*)d_out;

    fused_all<<<NB, 256>>>(boxes, scores, preds, out);
}

// round 17
// speedup vs baseline: 1.0667x; 1.0667x over previous
#include <cuda_runtime.h>
#include <cuda_bf16.h>
#include <cstdint>

// Problem constants
#define BB 4
#define NN 4096
#define CC 64
#define BN (BB * NN)
#define CHUNK 512
#define NCH (NN / CHUNK)          // 8 chunks per batch

#define TARGETF 560.0f
#define MIN_BOXF 5.0f
#define IOU_THRF 0.2f
#define CONF_THRF 0.001f
#define BOX_CONF_THRF 0.01f
#define MAX_WHF 4096.0f

#define CAP 256                    // per-class member cap for fast path
#define WSTRIDE 8                  // mask words per row (CAP/32)

// ------------------------- scratch (static device memory) -------------------
__device__ float4 g_cbox[BN];                      // clipped boxes, orig order
__device__ float  g_key[BN];                       // valid ? conf : -1
__device__ __align__(128) unsigned char g_tag[BN]; // valid ? cls : 255
__device__ unsigned long long g_ck[BN];            // sorted key chunks
__device__ float4 g_sbox[BN];                      // boxes in sorted order
__device__ float  g_sconf[BN];                     // conf in sorted order
__device__ __align__(128) unsigned char g_stag[BN];// tags in sorted order

// ------------------------- K1: conf / argmax / clip / valid -----------------
__global__ void k1_prepare(const float* __restrict__ boxes,
                           const float* __restrict__ scores,
                           const float* __restrict__ preds) {
    int warp = (blockIdx.x * blockDim.x + threadIdx.x) >> 5;
    int lane = threadIdx.x & 31;
    int half = lane >> 4;            // 0 or 1
    int hl   = lane & 15;            // lane within half
    int box  = warp * 2 + half;
    if (box >= BN) return;

    float s = scores[box];
    const float4* p4 = reinterpret_cast<const float4*>(preds + (size_t)box * CC);
    float4 pv = p4[hl];

    float bv; int bi;
    {
        float v0 = __fmul_rn(pv.x, s);
        float v1 = __fmul_rn(pv.y, s);
        float v2 = __fmul_rn(pv.z, s);
        float v3 = __fmul_rn(pv.w, s);
        bv = v0; bi = hl * 4;
        if (v1 > bv) { bv = v1; bi = hl * 4 + 1; }
        if (v2 > bv) { bv = v2; bi = hl * 4 + 2; }
        if (v3 > bv) { bv = v3; bi = hl * 4 + 3; }
    }

    #pragma unroll
    for (int o = 8; o > 0; o >>= 1) {
        float ov = __shfl_xor_sync(0xffffffffu, bv, o);
        int   oi = __shfl_xor_sync(0xffffffffu, bi, o);
        if (ov > bv || (ov == bv && oi < bi)) { bv = ov; bi = oi; }
    }

    if (hl == 0) {
        float4 bx = reinterpret_cast<const float4*>(boxes)[box];
        float x1 = fminf(fmaxf(bx.x, 0.0f), TARGETF);
        float y1 = fminf(fmaxf(bx.y, 0.0f), TARGETF);
        float x2 = fminf(fmaxf(bx.z, 0.0f), TARGETF);
        float y2 = fminf(fmaxf(bx.w, 0.0f), TARGETF);
        float w = __fsub_rn(x2, x1);
        float h = __fsub_rn(y2, y1);
        int valid = (s > BOX_CONF_THRF) && (w > MIN_BOXF) && (h > MIN_BOXF)
                    && (bv > CONF_THRF);
        g_cbox[box] = make_float4(x1, y1, x2, y2);
        g_key[box]  = valid ? bv : -1.0f;
        g_tag[box]  = valid ? (unsigned char)bi : (unsigned char)255;
    }
}

// ------------------------- register bitonic helpers -------------------------
__device__ __forceinline__ unsigned long long kmin(unsigned long long a,
                                                   unsigned long long b) {
    return a < b ? a : b;
}
__device__ __forceinline__ unsigned long long kmax(unsigned long long a,
                                                   unsigned long long b) {
    return a > b ? a : b;
}
__device__ __forceinline__ void stage_j(unsigned long long v[4], int i0,
                                        int lane, int k, int j) {
    if (j >= 4) {
        int m = j >> 2;
        #pragma unroll
        for (int r = 0; r < 4; r++) {
            unsigned long long other = __shfl_xor_sync(0xffffffffu, v[r], m);
            bool up = (((i0 + r) & k) == 0);
            bool keepmin = (((lane & m) == 0) == up);
            v[r] = keepmin ? kmin(v[r], other) : kmax(v[r], other);
        }
    } else if (j == 2) {
        #pragma unroll
        for (int r = 0; r < 2; r++) {
            bool up = (((i0 + r) & k) == 0);
            unsigned long long a = v[r], c = v[r + 2];
            if ((a > c) == up) { v[r] = c; v[r + 2] = a; }
        }
    } else {
        #pragma unroll
        for (int r = 0; r < 4; r += 2) {
            bool up = (((i0 + r) & k) == 0);
            unsigned long long a = v[r], c = v[r + 1];
            if ((a > c) == up) { v[r] = c; v[r + 1] = a; }
        }
    }
}

// ------------------------- K2a: chunk sort (512 keys/block) -----------------
__global__ void __launch_bounds__(128) k2a_chunksort() {
    int b  = blockIdx.x >> 3;
    int ch = blockIdx.x & 7;
    __shared__ unsigned long long sk[CHUNK];
    int tid  = threadIdx.x;
    int lane = tid & 31;
    int i0   = ((tid >> 5) << 7) + (lane << 2);

    #pragma unroll
    for (int u = 0; u < 4; u++) {
        int i   = tid + u * 128;
        int idx = ch * CHUNK + i;
        unsigned int x = __float_as_uint(g_key[b * NN + idx]);
        x = (x & 0x80000000u) ? ~x : (x | 0x80000000u);
        sk[i] = ((unsigned long long)(~x) << 32) | (unsigned int)idx;
    }
    __syncthreads();

    {
        unsigned long long v[4];
        #pragma unroll
        for (int r = 0; r < 4; r++) v[r] = sk[i0 + r];
        #pragma unroll
        for (int k = 2; k <= 128; k <<= 1)
            for (int j = k >> 1; j >= 1; j >>= 1)
                stage_j(v, i0, lane, k, j);
        #pragma unroll
        for (int r = 0; r < 4; r++) sk[i0 + r] = v[r];
    }
    __syncthreads();

    #pragma unroll
    for (int k = 256; k <= CHUNK; k <<= 1) {
        for (int j = k >> 1; j >= 128; j >>= 1) {
            #pragma unroll 2
            for (int u = 0; u < 2; u++) {
                int p   = tid + u * 128;
                int i   = ((p & ~(j - 1)) << 1) | (p & (j - 1));
                int ixj = i | j;
                bool up = ((i & k) == 0);
                unsigned long long a = sk[i], c = sk[ixj];
                if ((a > c) == up) { sk[i] = c; sk[ixj] = a; }
            }
            __syncthreads();
        }
        {
            unsigned long long v[4];
            #pragma unroll
            for (int r = 0; r < 4; r++) v[r] = sk[i0 + r];
            #pragma unroll
            for (int j = 64; j >= 1; j >>= 1)
                stage_j(v, i0, lane, k, j);
            #pragma unroll
            for (int r = 0; r < 4; r++) sk[i0 + r] = v[r];
        }
        __syncthreads();
    }

    #pragma unroll
    for (int u = 0; u < 4; u++) {
        int i = tid + u * 128;
        g_ck[b * NN + ch * CHUNK + i] = sk[i];
    }
}

// ------------------------- K2m: smem rank-merge + scatter + zero-out --------
__global__ void __launch_bounds__(CHUNK) k2m_merge(float* __restrict__ out) {
    int b  = blockIdx.x >> 3;
    int ch = blockIdx.x & 7;
    int tid = threadIdx.x;

    __shared__ unsigned long long sck[NN];          // 32KB
    const unsigned long long* ck = g_ck + b * NN;
    #pragma unroll
    for (int u = 0; u < NCH; u++) sck[tid + u * CHUNK] = ck[tid + u * CHUNK];
    __syncthreads();

    unsigned long long K = sck[ch * CHUNK + tid];
    int rank = tid;

    int lo[NCH], hi[NCH];
    #pragma unroll
    for (int c2 = 0; c2 < NCH; c2++) { lo[c2] = 0; hi[c2] = (c2 == ch) ? 0 : CHUNK; }

    #pragma unroll
    for (int it = 0; it < 10; it++) {
        #pragma unroll
        for (int c2 = 0; c2 < NCH; c2++) {
            if (lo[c2] < hi[c2]) {
                int mid = (lo[c2] + hi[c2]) >> 1;
                unsigned long long v = sck[c2 * CHUNK + mid];
                if (v < K) lo[c2] = mid + 1; else hi[c2] = mid;
            }
        }
    }
    #pragma unroll
    for (int c2 = 0; c2 < NCH; c2++) rank += lo[c2];

    int idx = (int)(K & 0xffffffffull);
    int d = b * NN + rank;
    int s = b * NN + idx;

    float* o = out + (size_t)d * 6;
    o[0] = 0.0f; o[1] = 0.0f; o[2] = 0.0f;
    o[3] = 0.0f; o[4] = 0.0f; o[5] = 0.0f;

    g_sbox[d] = g_cbox[s];
    g_stag[d] = g_tag[s];
    unsigned int up = ~(unsigned int)(K >> 32);
    unsigned int u  = (up & 0x80000000u) ? (up & 0x7fffffffu) : ~up;
    g_sconf[d] = __uint_as_float(u);
}

// movmskb: 1 bit per byte (bit0 of each byte) packed into low nibble
__device__ __forceinline__ unsigned int movmsk4(unsigned int eqw) {
    return (((eqw & 0x01010101u) * 0x01020408u) >> 24) & 0xFu;
}

// ------------------------- K3: per-(batch,class) NMS, 512 threads ------------
// 16 warps: stage-1 scan over 8 tags/thread, bit-matrix rows spread over 16
// warps (~4 serial rows each), warp-cooperative ffs greedy, direct writes.
__global__ void __launch_bounds__(512) k3_nms(float* __restrict__ out) {
    int bc   = blockIdx.x;
    int b    = bc >> 6;
    int c    = bc & 63;
    int t    = threadIdx.x;
    int lane = t & 31;
    int wid  = t >> 5;

    __shared__ float sx1[CAP], sy1[CAP], sx2[CAP], sy2[CAP];  // 4KB
    __shared__ float sar[CAP], scf[CAP];                      // 2KB
    __shared__ int   spos[CAP];                               // 1KB
    __shared__ unsigned int smask[CAP * WSTRIDE];             // 8KB
    __shared__ unsigned char mb[512];                         // membership bits
    __shared__ unsigned char supb[512];                       // fallback suppress
    __shared__ int   warp_tot[16];
    __shared__ unsigned int keepw[WSTRIDE];

    // ---- Stage 1: membership (8 tags/thread) + block scan ----
    const uint2* tw = reinterpret_cast<const uint2*>(g_stag + b * NN);
    uint2 wa = tw[t];
    unsigned int cls4 = (unsigned int)c * 0x01010101u;
    unsigned int mbv =
          movmsk4(__vcmpeq4(wa.x, cls4))
        | (movmsk4(__vcmpeq4(wa.y, cls4)) << 4);
    mb[t] = (unsigned char)mbv;
    int cnt = __popc(mbv);

    int inc = cnt;
    #pragma unroll
    for (int o = 1; o < 32; o <<= 1) {
        int tmp = __shfl_up_sync(0xffffffffu, inc, o);
        if (lane >= o) inc += tmp;
    }
    if (lane == 31) warp_tot[wid] = inc;
    __syncthreads();

    int M = 0, pre = 0;
    #pragma unroll
    for (int w = 0; w < 16; w++) {
        int v = warp_tot[w];
        if (w < wid) pre += v;
        M += v;
    }
    if (M == 0) return;

    float offc = (float)c * MAX_WHF;   // exact in fp32
    int off = pre + (inc - cnt);
    int base = t * 8;

    if (M <= CAP) {
        // ---- Stage 2: direct per-thread gather into compacted slots ----
        unsigned int r = mbv;
        while (r) {
            int q = __ffs(r) - 1;
            int pos = base + q;
            int slot = off++;
            spos[slot] = pos;
            scf[slot]  = g_sconf[b * NN + pos];
            float4 bx = g_sbox[b * NN + pos];
            sx1[slot] = bx.x; sy1[slot] = bx.y;
            sx2[slot] = bx.z; sy2[slot] = bx.w;
            float ox1 = __fadd_rn(bx.x, offc), oy1 = __fadd_rn(bx.y, offc);
            float ox2 = __fadd_rn(bx.z, offc), oy2 = __fadd_rn(bx.w, offc);
            sar[slot] = __fmul_rn(__fsub_rn(ox2, ox1), __fsub_rn(oy2, oy1));
            r &= r - 1;
        }
        __syncthreads();

        // ---- Stage 3: pairwise IoU>thr bit-matrix (16 warps on rows) ----
        int W = (M + 31) >> 5;
        for (int i = wid; i < M; i += 16) {
            float ix1 = __fadd_rn(sx1[i], offc), iy1 = __fadd_rn(sy1[i], offc);
            float ix2 = __fadd_rn(sx2[i], offc), iy2 = __fadd_rn(sy2[i], offc);
            float ai  = sar[i];
            for (int cw = (i >> 5); cw < W; cw++) {
                int j = cw * 32 + lane;
                bool s = false;
                if (j < M && j > i) {
                    float jx1 = __fadd_rn(sx1[j], offc), jy1 = __fadd_rn(sy1[j], offc);
                    float jx2 = __fadd_rn(sx2[j], offc), jy2 = __fadd_rn(sy2[j], offc);
                    float aj  = sar[j];
                    float ltx = fmaxf(ix1, jx1), lty = fmaxf(iy1, jy1);
                    float rbx = fminf(ix2, jx2), rby = fminf(iy2, jy2);
                    float w = fmaxf(__fsub_rn(rbx, ltx), 0.0f);
                    float h = fmaxf(__fsub_rn(rby, lty), 0.0f);
                    float inter = __fmul_rn(w, h);
                    float denom = __fadd_rn(__fsub_rn(__fadd_rn(ai, aj), inter), 1e-9f);
                    s = __fdiv_rn(inter, denom) > IOU_THRF;
                }
                unsigned int bal = __ballot_sync(0xffffffffu, s);
                if (lane == 0) smask[i * WSTRIDE + cw] = bal;
            }
        }
        __syncthreads();

        // ---- Stage 4a: warp-cooperative ffs greedy (warp 0) ----
        if (wid == 0) {
            int W2 = (M + 31) >> 5;
            unsigned int rem = 0;
            if (lane < W2) {
                int rb = M - lane * 32;
                rem = (rb >= 32) ? 0xffffffffu : ((1u << rb) - 1u);
            }
            unsigned int keep = 0;
            for (;;) {
                unsigned int bal = __ballot_sync(0xffffffffu, rem != 0);
                if (!bal) break;
                int src = __ffs(bal) - 1;
                unsigned int word = __shfl_sync(0xffffffffu, rem, src);
                int i = (src << 5) + __ffs(word) - 1;
                if (lane == src) {
                    keep |= 1u << (i & 31);
                    rem  &= ~(1u << (i & 31));
                }
                unsigned int supr = (lane < W2 && lane >= (i >> 5))
                                  ? smask[i * WSTRIDE + lane] : 0u;
                rem &= ~supr;
            }
            if (lane < WSTRIDE) keepw[lane] = (lane < W2) ? keep : 0u;
        }
        __syncthreads();

        // ---- Stage 4b: write kept rows DIRECTLY to output at row spos ----
        for (int m = t; m < M; m += 512) {
            if ((keepw[m >> 5] >> (m & 31)) & 1u) {
                float* o = out + ((size_t)b * NN + spos[m]) * 6;
                o[0] = sx1[m]; o[1] = sy1[m]; o[2] = sx2[m]; o[3] = sy2[m];
                o[4] = scf[m]; o[5] = (float)c;
            }
        }
        return;
    }

    // ---- Fallback (M > CAP): bitmap greedy in position order (never hit) ---
    supb[t] = 0;
    __syncthreads();
    for (int w = 0; w < 512; w++) {
        unsigned int avail = (unsigned int)(mb[w] & (unsigned char)~supb[w]);
        while (avail) {
            int bit = __ffs(avail) - 1;
            int pos = w * 8 + bit;
            float4 bi = g_sbox[b * NN + pos];
            float ix1 = __fadd_rn(bi.x, offc), iy1 = __fadd_rn(bi.y, offc);
            float ix2 = __fadd_rn(bi.z, offc), iy2 = __fadd_rn(bi.w, offc);
            float ai  = __fmul_rn(__fsub_rn(ix2, ix1), __fsub_rn(iy2, iy1));
            if (t == 0) {
                float* o = out + ((size_t)b * NN + pos) * 6;
                o[0] = bi.x; o[1] = bi.y; o[2] = bi.z; o[3] = bi.w;
                o[4] = g_sconf[b * NN + pos];
                o[5] = (float)c;
            }
            unsigned int mymb = mb[t], mysup = supb[t];
            #pragma unroll
            for (int q = 0; q < 8; q++) {
                int j = t * 8 + q;
                if (j > pos && ((mymb >> q) & 1u) && !((mysup >> q) & 1u)) {
                    float4 bj = g_sbox[b * NN + j];
                    float jx1 = __fadd_rn(bj.x, offc), jy1 = __fadd_rn(bj.y, offc);
                    float jx2 = __fadd_rn(bj.z, offc), jy2 = __fadd_rn(bj.w, offc);
                    float aj  = __fmul_rn(__fsub_rn(jx2, jx1), __fsub_rn(jy2, jy1));
                    float ltx = fmaxf(ix1, jx1), lty = fmaxf(iy1, jy1);
                    float rbx = fminf(ix2, jx2), rby = fminf(iy2, jy2);
                    float wq = fmaxf(__fsub_rn(rbx, ltx), 0.0f);
                    float hq = fmaxf(__fsub_rn(rby, lty), 0.0f);
                    float inter = __fmul_rn(wq, hq);
                    float denom = __fadd_rn(__fsub_rn(__fadd_rn(ai, aj), inter), 1e-9f);
                    if (__fdiv_rn(inter, denom) > IOU_THRF) mysup |= 1u << q;
                }
            }
            supb[t] = (unsigned char)mysup;
            __syncthreads();
            avail = (unsigned int)(mb[w] & (unsigned char)~supb[w]);
            avail &= ~((bit >= 7) ? 0xffu : ((1u << (bit + 1)) - 1u));
            avail &= 0xffu;
        }
        __syncthreads();
    }
}

// ------------------------- launch -------------------------------------------
extern "C" void kernel_launch(void* const* d_in, const int* in_sizes, int n_in,
                              void* d_out, int out_size) {
    const float *boxes = nullptr, *scores = nullptr, *preds = nullptr;
    for (int i = 0; i < n_in; i++) {
        if (in_sizes[i] == BN * 4)       boxes  = (const float*)d_in[i];
        else if (in_sizes[i] == BN)      scores = (const float*)d_in[i];
        else if (in_sizes[i] == BN * CC) preds  = (const float*)d_in[i];
    }
    float* out = (float*)d_out;

    k1_prepare<<<(BN / 2 * 32 + 1023) / 1024, 1024>>>(boxes, scores, preds);
    k2a_chunksort<<<BB * NCH, 128>>>();
    k2m_merge<<<BB * NCH, CHUNK>>>(out);
    k3_nms<<<BB * CC, 512>>>(out);
}